// round 1
// baseline (speedup 1.0000x reference)
#include <cuda_runtime.h>
#include <cuda_bf16.h>
#include <math.h>

#define BATCH 2
#define SEQLEN 2048
#define D_MODEL 1024
#define D_STATE 16
#define D_CONV 4
#define D_INNER 2048
#define DT_RANK 64

#define BL (BATCH * SEQLEN)               // 4096 rows
#define XDBL_W (DT_RANK + 2 * D_STATE)    // 96

// ---------------- scratch (static device globals; no dynamic alloc) ----------------
__device__ float g_xz[(size_t)BL * 2 * D_INNER];     // (b,l,4096)  xi | z
__device__ float g_xc[(size_t)BL * D_INNER];         // conv+silu output
__device__ float g_xdbl[(size_t)BL * XDBL_W];        // dt_raw | B | C
__device__ float g_dt[(size_t)BL * D_INNER];         // softplus(dt)
__device__ float g_edt[(size_t)BL * D_INNER];        // exp(-dt)
__device__ float g_y[(size_t)BL * D_INNER];          // scan output (gated)

// ---------------- generic fp32 tiled GEMM ----------------
// C[M,N] = A[M,K(lda)] @ B[K,N]
// EPI==1: v = acc + bias[col]; C = softplus(v); C2 = exp(-softplus(v))
template<int BM, int BN, int BK, int TM, int TN, int EPI>
__global__ __launch_bounds__((BM / TM) * (BN / TN))
void sgemm_kernel(const float* __restrict__ A, int lda,
                  const float* __restrict__ B,
                  float* __restrict__ C, float* __restrict__ C2,
                  const float* __restrict__ bias,
                  int M, int N, int K)
{
    constexpr int THREADS = (BM / TM) * (BN / TN);
    __shared__ float As[BK][BM];
    __shared__ float Bs[BK][BN];

    const int tid  = threadIdx.x;
    const int tcol = tid % (BN / TN);
    const int trow = tid / (BN / TN);

    const float* Ab = A + (size_t)blockIdx.y * BM * lda;
    const float* Bb = B + (size_t)blockIdx.x * BN;

    float acc[TM][TN];
#pragma unroll
    for (int m = 0; m < TM; m++)
#pragma unroll
        for (int n = 0; n < TN; n++) acc[m][n] = 0.f;

    for (int k0 = 0; k0 < K; k0 += BK) {
        // load A tile (BM x BK), store transposed As[k][m]
#pragma unroll
        for (int i = tid * 4; i < BM * BK; i += THREADS * 4) {
            int r = i / BK, c = i % BK;
            float4 v = *(const float4*)(Ab + (size_t)r * lda + k0 + c);
            As[c + 0][r] = v.x; As[c + 1][r] = v.y;
            As[c + 2][r] = v.z; As[c + 3][r] = v.w;
        }
        // load B tile (BK x BN)
#pragma unroll
        for (int i = tid * 4; i < BK * BN; i += THREADS * 4) {
            int r = i / BN, c = i % BN;
            *(float4*)(&Bs[r][c]) = *(const float4*)(Bb + (size_t)(k0 + r) * N + c);
        }
        __syncthreads();

#pragma unroll
        for (int kk = 0; kk < BK; kk++) {
            float ra[TM], rb[TN];
#pragma unroll
            for (int m = 0; m < TM; m++) ra[m] = As[kk][trow * TM + m];
#pragma unroll
            for (int n = 0; n < TN; n++) rb[n] = Bs[kk][tcol * TN + n];
#pragma unroll
            for (int m = 0; m < TM; m++)
#pragma unroll
                for (int n = 0; n < TN; n++)
                    acc[m][n] += ra[m] * rb[n];
        }
        __syncthreads();
    }

#pragma unroll
    for (int m = 0; m < TM; m++) {
        int row = blockIdx.y * BM + trow * TM + m;
#pragma unroll
        for (int n = 0; n < TN; n++) {
            int col = blockIdx.x * BN + tcol * TN + n;
            float v = acc[m][n];
            if (EPI == 1) {
                v += bias[col];
                float sp = (v > 20.f) ? v : log1pf(expf(v));
                C [(size_t)row * N + col] = sp;
                C2[(size_t)row * N + col] = expf(-sp);
            } else {
                C[(size_t)row * N + col] = v;
            }
        }
    }
}

// ---------------- depthwise causal conv1d + silu ----------------
__global__ void conv_silu_kernel(const float* __restrict__ conv_w,
                                 const float* __restrict__ conv_b)
{
    int idx = blockIdx.x * blockDim.x + threadIdx.x;
    if (idx >= BATCH * SEQLEN * D_INNER) return;
    int d = idx % D_INNER;
    int l = (idx / D_INNER) % SEQLEN;
    int b = idx / (D_INNER * SEQLEN);

    const float* xcol = g_xz + (size_t)b * SEQLEN * (2 * D_INNER) + d; // xi part, column d
    float acc = conv_b[d];
#pragma unroll
    for (int k = 0; k < D_CONV; k++) {
        int ll = l - (D_CONV - 1) + k;
        if (ll >= 0) acc += conv_w[d * D_CONV + k] * xcol[(size_t)ll * (2 * D_INNER)];
    }
    float s = 1.f / (1.f + __expf(-acc));
    g_xc[idx] = acc * s;
}

// ---------------- fused selective scan + D*x + silu(z) gating ----------------
// block: 64 threads = 32 channels x 2 halves (8 states each); grid: BATCH * (D_INNER/32)
#define T_CHUNK 64
__global__ __launch_bounds__(64)
void scan_kernel(const float* __restrict__ A_log, const float* __restrict__ Dp)
{
    __shared__ float sdt [T_CHUNK][32];
    __shared__ float sedt[T_CHUNK][32];
    __shared__ float sx  [T_CHUNK][32];
    __shared__ float sz  [T_CHUNK][32];
    __shared__ float sBC [T_CHUNK][32];   // [0..15]=B, [16..31]=C
    __shared__ float sy  [T_CHUNK][32];

    const int tid  = threadIdx.x;          // 0..63
    const int b    = blockIdx.x >> 6;      // D_INNER/32 = 64 chunks per batch
    const int d0   = (blockIdx.x & 63) * 32;
    const int dl   = tid >> 1;             // 0..31
    const int half = tid & 1;
    const int d    = d0 + dl;

    // per-thread A values (8 states), check the A[d,n] = -(n+1) structure
    float Avals[8];
    bool structured = true;
#pragma unroll
    for (int j = 0; j < 8; j++) {
        int n = half * 8 + j;              // 0-indexed state
        float a = -expf(A_log[d * D_STATE + n]);
        Avals[j] = a;
        structured = structured && (fabsf(a + (float)(n + 1)) < 1e-3f * (float)(n + 1));
    }
    const float Dv = Dp[d];

    float h[8];
#pragma unroll
    for (int j = 0; j < 8; j++) h[j] = 0.f;

    const size_t base_row = (size_t)b * SEQLEN;

    for (int l0 = 0; l0 < SEQLEN; l0 += T_CHUNK) {
        // cooperative staging: thread t loads row (l0+t)
        {
            const size_t row = base_row + l0 + tid;
            const float4* pdt  = (const float4*)(g_dt   + row * D_INNER + d0);
            const float4* pedt = (const float4*)(g_edt  + row * D_INNER + d0);
            const float4* px   = (const float4*)(g_xc   + row * D_INNER + d0);
            const float4* pz   = (const float4*)(g_xz   + row * (2 * D_INNER) + D_INNER + d0);
            const float4* pbc  = (const float4*)(g_xdbl + row * XDBL_W + DT_RANK);
#pragma unroll
            for (int q = 0; q < 8; q++) {
                *(float4*)&sdt [tid][q * 4] = pdt[q];
                *(float4*)&sedt[tid][q * 4] = pedt[q];
                *(float4*)&sx  [tid][q * 4] = px[q];
                *(float4*)&sz  [tid][q * 4] = pz[q];
                *(float4*)&sBC [tid][q * 4] = pbc[q];
            }
        }
        __syncthreads();

        for (int t = 0; t < T_CHUNK; t++) {
            float dt = sdt[t][dl];
            float x  = sx [t][dl];
            float dA[8];
            if (structured) {
                float e1 = sedt[t][dl];
                float e2 = e1 * e1;
                float e4 = e2 * e2;
                float p  = half ? (e4 * e4) : 1.0f;   // e^8 offset for upper half
#pragma unroll
                for (int j = 0; j < 8; j++) { p *= e1; dA[j] = p; }
            } else {
#pragma unroll
                for (int j = 0; j < 8; j++) dA[j] = __expf(dt * Avals[j]);
            }
            float dtx = dt * x;
            float y0 = 0.f, y1 = 0.f;
#pragma unroll
            for (int j = 0; j < 8; j++) {
                float Bn = sBC[t][half * 8 + j];
                float Cn = sBC[t][16 + half * 8 + j];
                h[j] = dA[j] * h[j] + dtx * Bn;
                if (j & 1) y1 += h[j] * Cn; else y0 += h[j] * Cn;
            }
            float y = y0 + y1;
            y += __shfl_xor_sync(0xffffffffu, y, 1);
            if (half == 0) {
                float zv  = sz[t][dl];
                float sig = 1.f / (1.f + __expf(-zv));
                sy[t][dl] = (y + Dv * x) * (zv * sig);
            }
        }
        __syncthreads();

        // store y chunk
        {
            const size_t row = base_row + l0 + tid;
            float4* py = (float4*)(g_y + row * D_INNER + d0);
#pragma unroll
            for (int q = 0; q < 8; q++) py[q] = *(const float4*)&sy[tid][q * 4];
        }
        __syncthreads();
    }
}

// ---------------- launch ----------------
extern "C" void kernel_launch(void* const* d_in, const int* in_sizes, int n_in,
                              void* d_out, int out_size)
{
    const float* x      = (const float*)d_in[0];  // (2,2048,1024)
    const float* W_in   = (const float*)d_in[1];  // (1024,4096)
    const float* conv_w = (const float*)d_in[2];  // (2048,1,4)
    const float* conv_b = (const float*)d_in[3];  // (2048,)
    const float* W_x    = (const float*)d_in[4];  // (2048,96)
    const float* W_dt   = (const float*)d_in[5];  // (64,2048)
    const float* b_dt   = (const float*)d_in[6];  // (2048,)
    const float* A_log  = (const float*)d_in[7];  // (2048,16)
    const float* Dp     = (const float*)d_in[8];  // (2048,)
    const float* W_out  = (const float*)d_in[9];  // (2048,1024)
    float* out = (float*)d_out;

    float* xz   = nullptr; cudaGetSymbolAddress((void**)&xz,   g_xz);
    float* xc   = nullptr; cudaGetSymbolAddress((void**)&xc,   g_xc);
    float* xdbl = nullptr; cudaGetSymbolAddress((void**)&xdbl, g_xdbl);
    float* dtp  = nullptr; cudaGetSymbolAddress((void**)&dtp,  g_dt);
    float* edtp = nullptr; cudaGetSymbolAddress((void**)&edtp, g_edt);
    float* yp   = nullptr; cudaGetSymbolAddress((void**)&yp,   g_y);

    // 1) xz = x @ W_in      (4096 x 4096 x K=1024)
    {
        dim3 grid(2 * D_INNER / 128, BL / 128);
        sgemm_kernel<128, 128, 16, 8, 8, 0><<<grid, 256>>>(
            x, D_MODEL, W_in, xz, nullptr, nullptr, BL, 2 * D_INNER, D_MODEL);
    }
    // 2) depthwise causal conv + silu -> xc
    {
        int total = BATCH * SEQLEN * D_INNER;
        conv_silu_kernel<<<(total + 255) / 256, 256>>>(conv_w, conv_b);
    }
    // 3) x_dbl = xc @ W_x   (4096 x 96 x K=2048)
    {
        dim3 grid(XDBL_W / 32, BL / 64);
        sgemm_kernel<64, 32, 16, 4, 4, 0><<<grid, 128>>>(
            xc, D_INNER, W_x, xdbl, nullptr, nullptr, BL, XDBL_W, D_INNER);
    }
    // 4) dt = softplus(x_dbl[:, :64] @ W_dt + b_dt); also exp(-dt)
    {
        dim3 grid(D_INNER / 128, BL / 128);
        sgemm_kernel<128, 128, 16, 8, 8, 1><<<grid, 256>>>(
            xdbl, XDBL_W, W_dt, dtp, edtp, b_dt, BL, D_INNER, DT_RANK);
    }
    // 5) selective scan (fused with D*x + silu(z) gating) -> y
    {
        scan_kernel<<<BATCH * (D_INNER / 32), 64>>>(A_log, Dp);
    }
    // 6) out = y @ W_out    (4096 x 1024 x K=2048)
    {
        dim3 grid(D_MODEL / 128, BL / 128);
        sgemm_kernel<128, 128, 16, 8, 8, 0><<<grid, 256>>>(
            yp, D_INNER, W_out, out, nullptr, nullptr, BL, D_MODEL, D_INNER);
    }
}

// round 4
// speedup vs baseline: 2.0487x; 2.0487x over previous
#include <cuda_runtime.h>
#include <cuda_bf16.h>
#include <math.h>
#include <stdint.h>

#define BATCH 2
#define SEQLEN 2048
#define D_MODEL 1024
#define D_STATE 16
#define D_CONV 4
#define D_INNER 2048
#define DT_RANK 64

#define BL (BATCH * SEQLEN)               // 4096 rows
#define XDBL_W (DT_RANK + 2 * D_STATE)    // 96

// ---------------- scratch (static device globals; no dynamic alloc) ----------------
__device__ float g_xr[(size_t)BL * D_MODEL];         // tf32-rounded x
__device__ float g_xz[(size_t)BL * 2 * D_INNER];     // (b,l,4096)  xi | z
__device__ float g_xc[(size_t)BL * D_INNER];         // conv+silu output (tf32-rounded)
__device__ float g_xdbl[(size_t)BL * XDBL_W];        // dt_raw | B | C (tf32-rounded)
__device__ float g_dt[(size_t)BL * D_INNER];         // softplus(dt)
__device__ float g_edt[(size_t)BL * D_INNER];        // exp(-dt)
__device__ float g_y[(size_t)BL * D_INNER];          // scan output (tf32-rounded)
// transposed (K-major, tf32-rounded) weights
__device__ float g_wtin[(size_t)(2 * D_INNER) * D_MODEL];   // [4096][1024]
__device__ float g_wtx[(size_t)128 * D_INNER];              // [128][2048] (96 padded w/ 0)
__device__ float g_wtdt[(size_t)D_INNER * DT_RANK];         // [2048][64]
__device__ float g_wtout[(size_t)D_MODEL * D_INNER];        // [1024][2048]

// ================= helpers =================
__device__ __forceinline__ uint32_t smem_u32(const void* p) {
    uint32_t a;
    asm("{ .reg .u64 t; cvta.to.shared.u64 t, %1; cvt.u32.u64 %0, t; }" : "=r"(a) : "l"(p));
    return a;
}
__device__ __forceinline__ float rna_tf32(float v) {
    uint32_t u;
    asm("cvt.rna.tf32.f32 %0, %1;" : "=r"(u) : "f"(v));
    return __uint_as_float(u);
}
#define CP_ASYNC16(dst, src) \
    asm volatile("cp.async.cg.shared.global [%0], [%1], 16;" :: "r"(dst), "l"(src) : "memory")
#define CP_COMMIT() asm volatile("cp.async.commit_group;" ::: "memory")
#define CP_WAIT0()  asm volatile("cp.async.wait_group 0;" ::: "memory")

__device__ __forceinline__ void mma_tf32(float* c, const uint32_t* a, uint32_t b0, uint32_t b1) {
    asm volatile(
        "mma.sync.aligned.m16n8k8.row.col.f32.tf32.tf32.f32 "
        "{%0,%1,%2,%3}, {%4,%5,%6,%7}, {%8,%9}, {%0,%1,%2,%3};"
        : "+f"(c[0]), "+f"(c[1]), "+f"(c[2]), "+f"(c[3])
        : "r"(a[0]), "r"(a[1]), "r"(a[2]), "r"(a[3]), "r"(b0), "r"(b1));
}
__device__ __forceinline__ uint32_t lds32(uint32_t addr) {
    uint32_t v;
    asm volatile("ld.shared.b32 %0, [%1];" : "=r"(v) : "r"(addr));
    return v;
}

// async tile load: 128 rows x 32 floats (128B/row), SW128 swizzle on 16B units
__device__ __forceinline__ void load_tile(const float* __restrict__ G, int ldg,
                                          uint32_t sbase, int k0, int tid) {
#pragma unroll
    for (int u = 0; u < 8; u++) {
        int i = tid + u * 128;
        int row = i >> 3, cu = i & 7;
        const float* src = G + (size_t)row * ldg + k0 + cu * 4;
        uint32_t off = (uint32_t)(row * 128 + ((cu ^ (row & 7)) << 4));
        CP_ASYNC16(sbase + off, src);
    }
}

// ---------------- tf32 mma.sync GEMM: C[M,N] = A[M,K] @ Bt[N,K]^T ----------------
// 128x128x32 CTA tile, 4 warps of 64x64 (m16n8k8), cp.async double buffer.
// EPI: 0 = plain store, 1 = softplus/exp(-) epilogue (dt), 2 = store tf32-rounded
template<int EPI>
__global__ __launch_bounds__(128, 2)
void mma_gemm(const float* __restrict__ A, int lda,
              const float* __restrict__ Bt, int ldb,
              float* __restrict__ C, float* __restrict__ C2,
              const float* __restrict__ bias,
              int ldc, int nvalid, int K)
{
    extern __shared__ float sm[];
    const uint32_t sb = smem_u32(sm);
    // stage s: A @ s*32768, B @ s*32768 + 16384
    const int tid = threadIdx.x;
    const int wid = tid >> 5, lane = tid & 31;
    const int wm = (wid & 1) * 64, wn = (wid >> 1) * 64;
    const int q = lane >> 2, t4 = lane & 3;

    const float* Ab = A  + (size_t)blockIdx.y * 128 * lda;
    const float* Bb = Bt + (size_t)blockIdx.x * 128 * ldb;

    float acc[4][8][4];
#pragma unroll
    for (int a = 0; a < 4; a++)
#pragma unroll
        for (int b = 0; b < 8; b++)
#pragma unroll
            for (int e = 0; e < 4; e++) acc[a][b][e] = 0.f;

    load_tile(Ab, lda, sb, 0, tid);
    load_tile(Bb, ldb, sb + 16384u, 0, tid);
    CP_COMMIT();

    const int niter = K >> 5;
    for (int it = 0; it < niter; it++) {
        CP_WAIT0();
        __syncthreads();
        if (it + 1 < niter) {
            uint32_t s2 = ((it + 1) & 1) ? 32768u : 0u;
            load_tile(Ab, lda, sb + s2, (it + 1) << 5, tid);
            load_tile(Bb, ldb, sb + s2 + 16384u, (it + 1) << 5, tid);
            CP_COMMIT();
        }
        const uint32_t abase = sb + ((it & 1) ? 32768u : 0u);
        const uint32_t bbase = abase + 16384u;
#pragma unroll
        for (int kk = 0; kk < 4; kk++) {
            const uint32_t x0 = (uint32_t)(((kk * 2) ^ q) << 4);
            const uint32_t x1 = (uint32_t)(((kk * 2 + 1) ^ q) << 4);
            uint32_t ar[4][4];
#pragma unroll
            for (int mf = 0; mf < 4; mf++) {
                uint32_t base = abase + (uint32_t)((wm + mf * 16 + q) * 128 + t4 * 4);
                ar[mf][0] = lds32(base + x0);
                ar[mf][1] = lds32(base + 1024u + x0);
                ar[mf][2] = lds32(base + x1);
                ar[mf][3] = lds32(base + 1024u + x1);
            }
#pragma unroll
            for (int nf = 0; nf < 8; nf++) {
                uint32_t bbb = bbase + (uint32_t)((wn + nf * 8 + q) * 128 + t4 * 4);
                uint32_t b0 = lds32(bbb + x0);
                uint32_t b1 = lds32(bbb + x1);
#pragma unroll
                for (int mf = 0; mf < 4; mf++)
                    mma_tf32(acc[mf][nf], ar[mf], b0, b1);
            }
        }
        __syncthreads();
    }

    // epilogue
#pragma unroll
    for (int mf = 0; mf < 4; mf++) {
        const int row = blockIdx.y * 128 + wm + mf * 16 + q;
#pragma unroll
        for (int nf = 0; nf < 8; nf++) {
            const int col = blockIdx.x * 128 + wn + nf * 8 + t4 * 2;
            float c0 = acc[mf][nf][0], c1 = acc[mf][nf][1];
            float c2 = acc[mf][nf][2], c3 = acc[mf][nf][3];
            if (EPI == 1) {
                const float bv0 = bias[col], bv1 = bias[col + 1];
                float v0 = c0 + bv0, v1 = c1 + bv1, v2 = c2 + bv0, v3 = c3 + bv1;
                float s0 = (v0 > 20.f) ? v0 : log1pf(expf(v0));
                float s1 = (v1 > 20.f) ? v1 : log1pf(expf(v1));
                float s2 = (v2 > 20.f) ? v2 : log1pf(expf(v2));
                float s3 = (v3 > 20.f) ? v3 : log1pf(expf(v3));
                *(float2*)(C  + (size_t)row * ldc + col)       = make_float2(s0, s1);
                *(float2*)(C  + (size_t)(row + 8) * ldc + col) = make_float2(s2, s3);
                *(float2*)(C2 + (size_t)row * ldc + col)       = make_float2(expf(-s0), expf(-s1));
                *(float2*)(C2 + (size_t)(row + 8) * ldc + col) = make_float2(expf(-s2), expf(-s3));
            } else {
                if (EPI == 2) {
                    c0 = rna_tf32(c0); c1 = rna_tf32(c1);
                    c2 = rna_tf32(c2); c3 = rna_tf32(c3);
                }
                if (col + 1 < nvalid) {
                    *(float2*)(C + (size_t)row * ldc + col)       = make_float2(c0, c1);
                    *(float2*)(C + (size_t)(row + 8) * ldc + col) = make_float2(c2, c3);
                }
            }
        }
    }
}

// ---------------- tf32 rounding pre-pass ----------------
__global__ void round_tf32_kernel(const float* __restrict__ src, float* __restrict__ dst, int n4)
{
    int i = blockIdx.x * blockDim.x + threadIdx.x;
    if (i < n4) {
        float4 v = ((const float4*)src)[i];
        v.x = rna_tf32(v.x); v.y = rna_tf32(v.y);
        v.z = rna_tf32(v.z); v.w = rna_tf32(v.w);
        ((float4*)dst)[i] = v;
    }
}

// ---------------- transpose (+ zero pad rows, tf32 rounding) ----------------
__global__ void transpose_pad(const float* __restrict__ src, float* __restrict__ dst,
                              int R, int C, int Cpad)
{
    __shared__ float t[32][33];
    const int bx = blockIdx.x * 32;
    const int by = blockIdx.y * 32;
    const int tx = threadIdx.x, ty = threadIdx.y;
#pragma unroll
    for (int j = 0; j < 32; j += 8) {
        int rr = by + ty + j, cc = bx + tx;
        float v = (cc < C && rr < R) ? src[(size_t)rr * C + cc] : 0.f;
        t[ty + j][tx] = rna_tf32(v);
    }
    __syncthreads();
#pragma unroll
    for (int j = 0; j < 32; j += 8) {
        int dr = bx + ty + j, dc = by + tx;
        if (dr < Cpad && dc < R)
            dst[(size_t)dr * R + dc] = t[tx][ty + j];
    }
}

// ---------------- depthwise causal conv1d + silu (tf32-rounded out) ----------------
__global__ void conv_silu_kernel(const float* __restrict__ conv_w,
                                 const float* __restrict__ conv_b)
{
    int idx = blockIdx.x * blockDim.x + threadIdx.x;
    if (idx >= BATCH * SEQLEN * D_INNER) return;
    int d = idx % D_INNER;
    int l = (idx / D_INNER) % SEQLEN;
    int b = idx / (D_INNER * SEQLEN);

    const float* xcol = g_xz + (size_t)b * SEQLEN * (2 * D_INNER) + d;
    float acc = conv_b[d];
#pragma unroll
    for (int k = 0; k < D_CONV; k++) {
        int ll = l - (D_CONV - 1) + k;
        if (ll >= 0) acc += conv_w[d * D_CONV + k] * xcol[(size_t)ll * (2 * D_INNER)];
    }
    float s = 1.f / (1.f + __expf(-acc));
    g_xc[idx] = rna_tf32(acc * s);
}

// ---------------- fused selective scan + D*x + silu(z) gating ----------------
#define T_CHUNK 64
__global__ __launch_bounds__(64)
void scan_kernel(const float* __restrict__ A_log, const float* __restrict__ Dp)
{
    __shared__ float sdt [T_CHUNK][32];
    __shared__ float sedt[T_CHUNK][32];
    __shared__ float sx  [T_CHUNK][32];
    __shared__ float sz  [T_CHUNK][32];
    __shared__ float sBC [T_CHUNK][32];
    __shared__ float sy  [T_CHUNK][32];

    const int tid  = threadIdx.x;
    const int b    = blockIdx.x >> 6;
    const int d0   = (blockIdx.x & 63) * 32;
    const int dl   = tid >> 1;
    const int half = tid & 1;
    const int d    = d0 + dl;

    float Avals[8];
    bool structured = true;
#pragma unroll
    for (int j = 0; j < 8; j++) {
        int n = half * 8 + j;
        float a = -expf(A_log[d * D_STATE + n]);
        Avals[j] = a;
        structured = structured && (fabsf(a + (float)(n + 1)) < 1e-3f * (float)(n + 1));
    }
    const float Dv = Dp[d];

    float h[8];
#pragma unroll
    for (int j = 0; j < 8; j++) h[j] = 0.f;

    const size_t base_row = (size_t)b * SEQLEN;

    for (int l0 = 0; l0 < SEQLEN; l0 += T_CHUNK) {
        {
            const size_t row = base_row + l0 + tid;
            const float4* pdt  = (const float4*)(g_dt   + row * D_INNER + d0);
            const float4* pedt = (const float4*)(g_edt  + row * D_INNER + d0);
            const float4* px   = (const float4*)(g_xc   + row * D_INNER + d0);
            const float4* pz   = (const float4*)(g_xz   + row * (2 * D_INNER) + D_INNER + d0);
            const float4* pbc  = (const float4*)(g_xdbl + row * XDBL_W + DT_RANK);
#pragma unroll
            for (int q = 0; q < 8; q++) {
                *(float4*)&sdt [tid][q * 4] = pdt[q];
                *(float4*)&sedt[tid][q * 4] = pedt[q];
                *(float4*)&sx  [tid][q * 4] = px[q];
                *(float4*)&sz  [tid][q * 4] = pz[q];
                *(float4*)&sBC [tid][q * 4] = pbc[q];
            }
        }
        __syncthreads();

        for (int t = 0; t < T_CHUNK; t++) {
            float dt = sdt[t][dl];
            float x  = sx [t][dl];
            float dA[8];
            if (structured) {
                float e1 = sedt[t][dl];
                float e2 = e1 * e1;
                float e4 = e2 * e2;
                float p  = half ? (e4 * e4) : 1.0f;
#pragma unroll
                for (int j = 0; j < 8; j++) { p *= e1; dA[j] = p; }
            } else {
#pragma unroll
                for (int j = 0; j < 8; j++) dA[j] = __expf(dt * Avals[j]);
            }
            float dtx = dt * x;
            float y0 = 0.f, y1 = 0.f;
#pragma unroll
            for (int j = 0; j < 8; j++) {
                float Bn = sBC[t][half * 8 + j];
                float Cn = sBC[t][16 + half * 8 + j];
                h[j] = dA[j] * h[j] + dtx * Bn;
                if (j & 1) y1 += h[j] * Cn; else y0 += h[j] * Cn;
            }
            float y = y0 + y1;
            y += __shfl_xor_sync(0xffffffffu, y, 1);
            if (half == 0) {
                float zv  = sz[t][dl];
                float sig = 1.f / (1.f + __expf(-zv));
                sy[t][dl] = rna_tf32((y + Dv * x) * (zv * sig));
            }
        }
        __syncthreads();

        {
            const size_t row = base_row + l0 + tid;
            float4* py = (float4*)(g_y + row * D_INNER + d0);
#pragma unroll
            for (int q = 0; q < 8; q++) py[q] = *(const float4*)&sy[tid][q * 4];
        }
        __syncthreads();
    }
}

// ---------------- launch ----------------
#define GEMM_SMEM 65536

extern "C" void kernel_launch(void* const* d_in, const int* in_sizes, int n_in,
                              void* d_out, int out_size)
{
    const float* x      = (const float*)d_in[0];
    const float* W_in   = (const float*)d_in[1];
    const float* conv_w = (const float*)d_in[2];
    const float* conv_b = (const float*)d_in[3];
    const float* W_x    = (const float*)d_in[4];
    const float* W_dt   = (const float*)d_in[5];
    const float* b_dt   = (const float*)d_in[6];
    const float* A_log  = (const float*)d_in[7];
    const float* Dp     = (const float*)d_in[8];
    const float* W_out  = (const float*)d_in[9];
    float* out = (float*)d_out;

    float* xr    = nullptr; cudaGetSymbolAddress((void**)&xr,    g_xr);
    float* xz    = nullptr; cudaGetSymbolAddress((void**)&xz,    g_xz);
    float* xc    = nullptr; cudaGetSymbolAddress((void**)&xc,    g_xc);
    float* xdbl  = nullptr; cudaGetSymbolAddress((void**)&xdbl,  g_xdbl);
    float* dtp   = nullptr; cudaGetSymbolAddress((void**)&dtp,   g_dt);
    float* edtp  = nullptr; cudaGetSymbolAddress((void**)&edtp,  g_edt);
    float* yp    = nullptr; cudaGetSymbolAddress((void**)&yp,    g_y);
    float* wtin  = nullptr; cudaGetSymbolAddress((void**)&wtin,  g_wtin);
    float* wtx   = nullptr; cudaGetSymbolAddress((void**)&wtx,   g_wtx);
    float* wtdt  = nullptr; cudaGetSymbolAddress((void**)&wtdt,  g_wtdt);
    float* wtout = nullptr; cudaGetSymbolAddress((void**)&wtout, g_wtout);

    cudaFuncSetAttribute(mma_gemm<0>, cudaFuncAttributeMaxDynamicSharedMemorySize, GEMM_SMEM);
    cudaFuncSetAttribute(mma_gemm<1>, cudaFuncAttributeMaxDynamicSharedMemorySize, GEMM_SMEM);
    cudaFuncSetAttribute(mma_gemm<2>, cudaFuncAttributeMaxDynamicSharedMemorySize, GEMM_SMEM);

    // tf32-round x
    round_tf32_kernel<<<(BL * D_MODEL / 4 + 255) / 256, 256>>>(x, xr, BL * D_MODEL / 4);

    // weight transposes (K-major, tf32-rounded)
    dim3 tb(32, 8);
    transpose_pad<<<dim3(4096 / 32, 1024 / 32), tb>>>(W_in,  wtin,  D_MODEL, 2 * D_INNER, 2 * D_INNER);
    transpose_pad<<<dim3(128 / 32,  2048 / 32), tb>>>(W_x,   wtx,   D_INNER, XDBL_W, 128);
    transpose_pad<<<dim3(2048 / 32, 64 / 32),   tb>>>(W_dt,  wtdt,  DT_RANK, D_INNER, D_INNER);
    transpose_pad<<<dim3(1024 / 32, 2048 / 32), tb>>>(W_out, wtout, D_INNER, D_MODEL, D_MODEL);

    // 1) xz = x @ W_in   (M=4096, N=4096, K=1024)
    mma_gemm<0><<<dim3(4096 / 128, BL / 128), 128, GEMM_SMEM>>>(
        xr, D_MODEL, wtin, D_MODEL, xz, nullptr, nullptr, 2 * D_INNER, 2 * D_INNER, D_MODEL);

    // 2) depthwise causal conv + silu (tf32-rounded out)
    {
        int total = BATCH * SEQLEN * D_INNER;
        conv_silu_kernel<<<(total + 255) / 256, 256>>>(conv_w, conv_b);
    }

    // 3) x_dbl = xc @ W_x  (M=4096, N=128 pad, K=2048) store 96 cols, tf32-rounded
    mma_gemm<2><<<dim3(1, BL / 128), 128, GEMM_SMEM>>>(
        xc, D_INNER, wtx, D_INNER, xdbl, nullptr, nullptr, XDBL_W, XDBL_W, D_INNER);

    // 4) dt = softplus(x_dbl[:, :64] @ W_dt + b_dt); edt = exp(-dt)  (M=4096, N=2048, K=64)
    mma_gemm<1><<<dim3(2048 / 128, BL / 128), 128, GEMM_SMEM>>>(
        xdbl, XDBL_W, wtdt, DT_RANK, dtp, edtp, b_dt, D_INNER, D_INNER, DT_RANK);

    // 5) selective scan
    scan_kernel<<<BATCH * (D_INNER / 32), 64>>>(A_log, Dp);

    // 6) out = y @ W_out   (M=4096, N=1024, K=2048)  — ldb = D_INNER (row stride of wtout)
    mma_gemm<0><<<dim3(1024 / 128, BL / 128), 128, GEMM_SMEM>>>(
        yp, D_INNER, wtout, D_INNER, out, nullptr, nullptr, D_MODEL, D_MODEL, D_INNER);
}

// round 5
// speedup vs baseline: 2.1927x; 1.0703x over previous
#include <cuda_runtime.h>
#include <cuda_bf16.h>
#include <math.h>
#include <stdint.h>

#define BATCH 2
#define SEQLEN 2048
#define D_MODEL 1024
#define D_STATE 16
#define D_CONV 4
#define D_INNER 2048
#define DT_RANK 64

#define BL (BATCH * SEQLEN)               // 4096 rows
#define XDBL_W (DT_RANK + 2 * D_STATE)    // 96
#define X3N (BL * XDBL_W)                 // 393216

// ---------------- scratch ----------------
__device__ float g_xr[(size_t)BL * D_MODEL];
__device__ float g_xz[(size_t)BL * 2 * D_INNER];
__device__ float g_xc[(size_t)BL * D_INNER];
__device__ float g_xdbl[(size_t)BL * XDBL_W];
__device__ float g_x3part[(size_t)4 * X3N];          // split-K partials for GEMM3
__device__ float g_dt[(size_t)BL * D_INNER];
__device__ float g_edt[(size_t)BL * D_INNER];
__device__ float g_y[(size_t)BL * D_INNER];
__device__ float g_wtin[(size_t)(2 * D_INNER) * D_MODEL];
__device__ float g_wtx[(size_t)128 * D_INNER];
__device__ float g_wtdt[(size_t)D_INNER * DT_RANK];
__device__ float g_wtout[(size_t)D_MODEL * D_INNER];

// ================= helpers =================
__device__ __forceinline__ uint32_t smem_u32(const void* p) {
    uint32_t a;
    asm("{ .reg .u64 t; cvta.to.shared.u64 t, %1; cvt.u32.u64 %0, t; }" : "=r"(a) : "l"(p));
    return a;
}
__device__ __forceinline__ float rna_tf32(float v) {
    uint32_t u;
    asm("cvt.rna.tf32.f32 %0, %1;" : "=r"(u) : "f"(v));
    return __uint_as_float(u);
}
#define CP_ASYNC16(dst, src) \
    asm volatile("cp.async.cg.shared.global [%0], [%1], 16;" :: "r"(dst), "l"(src) : "memory")
#define CP_COMMIT() asm volatile("cp.async.commit_group;" ::: "memory")
#define CP_WAIT0()  asm volatile("cp.async.wait_group 0;" ::: "memory")
#define CP_WAIT1()  asm volatile("cp.async.wait_group 1;" ::: "memory")

__device__ __forceinline__ void mma_tf32(float* c, const uint32_t* a, uint32_t b0, uint32_t b1) {
    asm volatile(
        "mma.sync.aligned.m16n8k8.row.col.f32.tf32.tf32.f32 "
        "{%0,%1,%2,%3}, {%4,%5,%6,%7}, {%8,%9}, {%0,%1,%2,%3};"
        : "+f"(c[0]), "+f"(c[1]), "+f"(c[2]), "+f"(c[3])
        : "r"(a[0]), "r"(a[1]), "r"(a[2]), "r"(a[3]), "r"(b0), "r"(b1));
}
__device__ __forceinline__ uint32_t lds32(uint32_t addr) {
    uint32_t v;
    asm volatile("ld.shared.b32 %0, [%1];" : "=r"(v) : "r"(addr));
    return v;
}

// async tile load: ROWS x 32 floats (128B/row), SW128 swizzle on 16B units
template<int ROWS, int THREADS>
__device__ __forceinline__ void load_tile(const float* __restrict__ G, int ldg,
                                          uint32_t sbase, int k0, int tid) {
#pragma unroll
    for (int u = 0; u < ROWS * 8 / THREADS; u++) {
        int i = tid + u * THREADS;
        int row = i >> 3, cu = i & 7;
        const float* src = G + (size_t)row * ldg + k0 + cu * 4;
        uint32_t off = (uint32_t)(row * 128 + ((cu ^ (row & 7)) << 4));
        CP_ASYNC16(sbase + off, src);
    }
}

// ---------------- tf32 mma.sync GEMM: C[M,N] = A[M,K] @ Bt[N,K]^T ----------------
// BM x 128 x 32 CTA tile, warps of 64x64. Split-K via blockIdx.z (kbase/csplit).
// EPI: 0 = plain store, 1 = softplus/exp(-) epilogue (dt)
template<int BM, int THREADS, int EPI>
__global__ __launch_bounds__(THREADS, (THREADS == 128) ? 2 : 1)
void mma_gemm(const float* __restrict__ A, int lda,
              const float* __restrict__ Bt, int ldb,
              float* __restrict__ C, float* __restrict__ C2,
              const float* __restrict__ bias,
              int ldc, int nvalid, int K, size_t csplit)
{
    extern __shared__ float sm[];
    const uint32_t sb = smem_u32(sm);
    constexpr uint32_t SS = (uint32_t)(BM + 128) * 128;  // bytes per stage
    constexpr int MW = BM / 64;

    const int tid = threadIdx.x;
    const int wid = tid >> 5, lane = tid & 31;
    const int wm = (wid % MW) * 64, wn = (wid / MW) * 64;
    const int q = lane >> 2, t4 = lane & 3;

    const int kbase = blockIdx.z * K;
    const float* Ab = A  + (size_t)blockIdx.y * BM * lda + kbase;
    const float* Bb = Bt + (size_t)blockIdx.x * 128 * ldb + kbase;
    C += csplit * blockIdx.z;

    float acc[4][8][4];
#pragma unroll
    for (int a = 0; a < 4; a++)
#pragma unroll
        for (int b = 0; b < 8; b++)
#pragma unroll
            for (int e = 0; e < 4; e++) acc[a][b][e] = 0.f;

    load_tile<BM, THREADS>(Ab, lda, sb, 0, tid);
    load_tile<128, THREADS>(Bb, ldb, sb + (uint32_t)BM * 128, 0, tid);
    CP_COMMIT();

    const int niter = K >> 5;
    for (int it = 0; it < niter; it++) {
        CP_WAIT0();
        __syncthreads();
        if (it + 1 < niter) {
            uint32_t s2 = ((it + 1) & 1) ? SS : 0u;
            load_tile<BM, THREADS>(Ab, lda, sb + s2, (it + 1) << 5, tid);
            load_tile<128, THREADS>(Bb, ldb, sb + s2 + (uint32_t)BM * 128, (it + 1) << 5, tid);
            CP_COMMIT();
        }
        const uint32_t abase = sb + ((it & 1) ? SS : 0u);
        const uint32_t bbase = abase + (uint32_t)BM * 128;
#pragma unroll
        for (int kk = 0; kk < 4; kk++) {
            const uint32_t x0 = (uint32_t)(((kk * 2) ^ q) << 4);
            const uint32_t x1 = (uint32_t)(((kk * 2 + 1) ^ q) << 4);
            uint32_t ar[4][4];
#pragma unroll
            for (int mf = 0; mf < 4; mf++) {
                uint32_t base = abase + (uint32_t)((wm + mf * 16 + q) * 128 + t4 * 4);
                ar[mf][0] = lds32(base + x0);
                ar[mf][1] = lds32(base + 1024u + x0);
                ar[mf][2] = lds32(base + x1);
                ar[mf][3] = lds32(base + 1024u + x1);
            }
#pragma unroll
            for (int nf = 0; nf < 8; nf++) {
                uint32_t bbb = bbase + (uint32_t)((wn + nf * 8 + q) * 128 + t4 * 4);
                uint32_t b0 = lds32(bbb + x0);
                uint32_t b1 = lds32(bbb + x1);
#pragma unroll
                for (int mf = 0; mf < 4; mf++)
                    mma_tf32(acc[mf][nf], ar[mf], b0, b1);
            }
        }
        __syncthreads();
    }

    // epilogue
#pragma unroll
    for (int mf = 0; mf < 4; mf++) {
        const int row = blockIdx.y * BM + wm + mf * 16 + q;
#pragma unroll
        for (int nf = 0; nf < 8; nf++) {
            const int col = blockIdx.x * 128 + wn + nf * 8 + t4 * 2;
            float c0 = acc[mf][nf][0], c1 = acc[mf][nf][1];
            float c2 = acc[mf][nf][2], c3 = acc[mf][nf][3];
            if (EPI == 1) {
                const float bv0 = bias[col], bv1 = bias[col + 1];
                float v0 = c0 + bv0, v1 = c1 + bv1, v2 = c2 + bv0, v3 = c3 + bv1;
                float s0 = (v0 > 20.f) ? v0 : log1pf(expf(v0));
                float s1 = (v1 > 20.f) ? v1 : log1pf(expf(v1));
                float s2 = (v2 > 20.f) ? v2 : log1pf(expf(v2));
                float s3 = (v3 > 20.f) ? v3 : log1pf(expf(v3));
                *(float2*)(C  + (size_t)row * ldc + col)       = make_float2(s0, s1);
                *(float2*)(C  + (size_t)(row + 8) * ldc + col) = make_float2(s2, s3);
                *(float2*)(C2 + (size_t)row * ldc + col)       = make_float2(expf(-s0), expf(-s1));
                *(float2*)(C2 + (size_t)(row + 8) * ldc + col) = make_float2(expf(-s2), expf(-s3));
            } else {
                if (col + 1 < nvalid) {
                    *(float2*)(C + (size_t)row * ldc + col)       = make_float2(c0, c1);
                    *(float2*)(C + (size_t)(row + 8) * ldc + col) = make_float2(c2, c3);
                }
            }
        }
    }
}

// ---------------- split-K reduce for GEMM3 (+ tf32 rounding) ----------------
__global__ void reduce_x3_kernel()
{
    int i = blockIdx.x * blockDim.x + threadIdx.x;
    const int n4 = X3N / 4;
    if (i >= n4) return;
    const float4* p = (const float4*)g_x3part;
    float4 a = p[i], b = p[i + n4], c = p[i + 2 * n4], d = p[i + 3 * n4];
    float4 r;
    r.x = rna_tf32(a.x + b.x + c.x + d.x);
    r.y = rna_tf32(a.y + b.y + c.y + d.y);
    r.z = rna_tf32(a.z + b.z + c.z + d.z);
    r.w = rna_tf32(a.w + b.w + c.w + d.w);
    ((float4*)g_xdbl)[i] = r;
}

// ---------------- tf32 rounding pre-pass ----------------
__global__ void round_tf32_kernel(const float* __restrict__ src, float* __restrict__ dst, int n4)
{
    int i = blockIdx.x * blockDim.x + threadIdx.x;
    if (i < n4) {
        float4 v = ((const float4*)src)[i];
        v.x = rna_tf32(v.x); v.y = rna_tf32(v.y);
        v.z = rna_tf32(v.z); v.w = rna_tf32(v.w);
        ((float4*)dst)[i] = v;
    }
}

// ---------------- transpose (+ zero pad rows, tf32 rounding) ----------------
__global__ void transpose_pad(const float* __restrict__ src, float* __restrict__ dst,
                              int R, int C, int Cpad)
{
    __shared__ float t[32][33];
    const int bx = blockIdx.x * 32;
    const int by = blockIdx.y * 32;
    const int tx = threadIdx.x, ty = threadIdx.y;
#pragma unroll
    for (int j = 0; j < 32; j += 8) {
        int rr = by + ty + j, cc = bx + tx;
        float v = (cc < C && rr < R) ? src[(size_t)rr * C + cc] : 0.f;
        t[ty + j][tx] = rna_tf32(v);
    }
    __syncthreads();
#pragma unroll
    for (int j = 0; j < 32; j += 8) {
        int dr = bx + ty + j, dc = by + tx;
        if (dr < Cpad && dc < R)
            dst[(size_t)dr * R + dc] = t[tx][ty + j];
    }
}

// ---------------- depthwise causal conv1d + silu ----------------
__global__ void conv_silu_kernel(const float* __restrict__ conv_w,
                                 const float* __restrict__ conv_b)
{
    int idx = blockIdx.x * blockDim.x + threadIdx.x;
    if (idx >= BATCH * SEQLEN * D_INNER) return;
    int d = idx % D_INNER;
    int l = (idx / D_INNER) % SEQLEN;
    int b = idx / (D_INNER * SEQLEN);

    const float* xcol = g_xz + (size_t)b * SEQLEN * (2 * D_INNER) + d;
    float acc = conv_b[d];
#pragma unroll
    for (int k = 0; k < D_CONV; k++) {
        int ll = l - (D_CONV - 1) + k;
        if (ll >= 0) acc += conv_w[d * D_CONV + k] * xcol[(size_t)ll * (2 * D_INNER)];
    }
    float s = 1.f / (1.f + __expf(-acc));
    g_xc[idx] = rna_tf32(acc * s);
}

// ---------------- fused selective scan (double-buffered staging) ----------------
#define T_CHUNK 64
#define NCHUNK (SEQLEN / T_CHUNK)
// smem float offsets (per block): 5 double-buffered input arrays + single y buffer
#define SC_DT  0
#define SC_EDT 4096
#define SC_X   8192
#define SC_Z   12288
#define SC_BC  16384
#define SC_Y   20480
#define SCAN_SMEM ((20480 + 2048) * 4)

__global__ __launch_bounds__(64)
void scan_kernel(const float* __restrict__ A_log, const float* __restrict__ Dp)
{
    extern __shared__ float sf[];
    const uint32_t sb = smem_u32(sf);

    const int tid  = threadIdx.x;
    const int b    = blockIdx.x >> 6;
    const int d0   = (blockIdx.x & 63) * 32;
    const int dl   = tid >> 1;
    const int half = tid & 1;
    const int d    = d0 + dl;

    float Avals[8];
    bool structured = true;
#pragma unroll
    for (int j = 0; j < 8; j++) {
        int n = half * 8 + j;
        float a = -expf(A_log[d * D_STATE + n]);
        Avals[j] = a;
        structured = structured && (fabsf(a + (float)(n + 1)) < 1e-3f * (float)(n + 1));
    }
    const float Dv = Dp[d];

    float h[8];
#pragma unroll
    for (int j = 0; j < 8; j++) h[j] = 0.f;

    const size_t base_row = (size_t)b * SEQLEN;

    // async stage loader: row (l0+tid) of each input array into buffer s
    auto stage = [&](int l0, int s) {
        const size_t row = base_row + l0 + tid;
        const uint32_t so = (uint32_t)(s * 8192) + (uint32_t)tid * 128;
        const float* pdt  = g_dt   + row * D_INNER + d0;
        const float* pedt = g_edt  + row * D_INNER + d0;
        const float* px   = g_xc   + row * D_INNER + d0;
        const float* pz   = g_xz   + row * (2 * D_INNER) + D_INNER + d0;
        const float* pbc  = g_xdbl + row * XDBL_W + DT_RANK;
#pragma unroll
        for (int qq = 0; qq < 8; qq++) {
            CP_ASYNC16(sb + SC_DT  * 4 + so + qq * 16, pdt  + qq * 4);
            CP_ASYNC16(sb + SC_EDT * 4 + so + qq * 16, pedt + qq * 4);
            CP_ASYNC16(sb + SC_X   * 4 + so + qq * 16, px   + qq * 4);
            CP_ASYNC16(sb + SC_Z   * 4 + so + qq * 16, pz   + qq * 4);
            CP_ASYNC16(sb + SC_BC  * 4 + so + qq * 16, pbc  + qq * 4);
        }
        CP_COMMIT();
    };

    stage(0, 0);

    for (int c = 0; c < NCHUNK; c++) {
        const int s = c & 1;
        if (c + 1 < NCHUNK) {
            stage((c + 1) * T_CHUNK, s ^ 1);
            CP_WAIT1();
        } else {
            CP_WAIT0();
        }
        __syncthreads();

        const float* fdt  = sf + SC_DT  + s * 2048;
        const float* fedt = sf + SC_EDT + s * 2048;
        const float* fx   = sf + SC_X   + s * 2048;
        const float* fz   = sf + SC_Z   + s * 2048;
        const float* fbc  = sf + SC_BC  + s * 2048;

        for (int t = 0; t < T_CHUNK; t++) {
            float dt = fdt[t * 32 + dl];
            float x  = fx [t * 32 + dl];
            float dA[8];
            if (structured) {
                float e1 = fedt[t * 32 + dl];
                float e2 = e1 * e1;
                float e4 = e2 * e2;
                float p  = half ? (e4 * e4) : 1.0f;
#pragma unroll
                for (int j = 0; j < 8; j++) { p *= e1; dA[j] = p; }
            } else {
#pragma unroll
                for (int j = 0; j < 8; j++) dA[j] = __expf(dt * Avals[j]);
            }
            float dtx = dt * x;
            float y0 = 0.f, y1 = 0.f;
#pragma unroll
            for (int j = 0; j < 8; j++) {
                float Bn = fbc[t * 32 + half * 8 + j];
                float Cn = fbc[t * 32 + 16 + half * 8 + j];
                h[j] = dA[j] * h[j] + dtx * Bn;
                if (j & 1) y1 += h[j] * Cn; else y0 += h[j] * Cn;
            }
            float y = y0 + y1;
            y += __shfl_xor_sync(0xffffffffu, y, 1);
            if (half == 0) {
                float zv  = fz[t * 32 + dl];
                float sig = 1.f / (1.f + __expf(-zv));
                sf[SC_Y + t * 32 + dl] = rna_tf32((y + Dv * x) * (zv * sig));
            }
        }
        __syncthreads();

        {
            const size_t row = base_row + c * T_CHUNK + tid;
            float4* py = (float4*)(g_y + row * D_INNER + d0);
#pragma unroll
            for (int qq = 0; qq < 8; qq++) py[qq] = *(const float4*)&sf[SC_Y + tid * 32 + qq * 4];
        }
        __syncthreads();
    }
}

// ---------------- launch ----------------
#define SMEM_128 65536
#define SMEM_256 98304

extern "C" void kernel_launch(void* const* d_in, const int* in_sizes, int n_in,
                              void* d_out, int out_size)
{
    const float* x      = (const float*)d_in[0];
    const float* W_in   = (const float*)d_in[1];
    const float* conv_w = (const float*)d_in[2];
    const float* conv_b = (const float*)d_in[3];
    const float* W_x    = (const float*)d_in[4];
    const float* W_dt   = (const float*)d_in[5];
    const float* b_dt   = (const float*)d_in[6];
    const float* A_log  = (const float*)d_in[7];
    const float* Dp     = (const float*)d_in[8];
    const float* W_out  = (const float*)d_in[9];
    float* out = (float*)d_out;

    float* xr    = nullptr; cudaGetSymbolAddress((void**)&xr,    g_xr);
    float* xz    = nullptr; cudaGetSymbolAddress((void**)&xz,    g_xz);
    float* xc    = nullptr; cudaGetSymbolAddress((void**)&xc,    g_xc);
    float* xdbl  = nullptr; cudaGetSymbolAddress((void**)&xdbl,  g_xdbl);
    float* x3p   = nullptr; cudaGetSymbolAddress((void**)&x3p,   g_x3part);
    float* dtp   = nullptr; cudaGetSymbolAddress((void**)&dtp,   g_dt);
    float* edtp  = nullptr; cudaGetSymbolAddress((void**)&edtp,  g_edt);
    float* yp    = nullptr; cudaGetSymbolAddress((void**)&yp,    g_y);
    float* wtin  = nullptr; cudaGetSymbolAddress((void**)&wtin,  g_wtin);
    float* wtx   = nullptr; cudaGetSymbolAddress((void**)&wtx,   g_wtx);
    float* wtdt  = nullptr; cudaGetSymbolAddress((void**)&wtdt,  g_wtdt);
    float* wtout = nullptr; cudaGetSymbolAddress((void**)&wtout, g_wtout);

    cudaFuncSetAttribute((const void*)mma_gemm<128, 128, 0>, cudaFuncAttributeMaxDynamicSharedMemorySize, SMEM_128);
    cudaFuncSetAttribute((const void*)mma_gemm<128, 128, 1>, cudaFuncAttributeMaxDynamicSharedMemorySize, SMEM_128);
    cudaFuncSetAttribute((const void*)mma_gemm<256, 256, 0>, cudaFuncAttributeMaxDynamicSharedMemorySize, SMEM_256);
    cudaFuncSetAttribute((const void*)scan_kernel, cudaFuncAttributeMaxDynamicSharedMemorySize, SCAN_SMEM);

    // tf32-round x
    round_tf32_kernel<<<(BL * D_MODEL / 4 + 255) / 256, 256>>>(x, xr, BL * D_MODEL / 4);

    // weight transposes (K-major, tf32-rounded)
    dim3 tb(32, 8);
    transpose_pad<<<dim3(4096 / 32, 1024 / 32), tb>>>(W_in,  wtin,  D_MODEL, 2 * D_INNER, 2 * D_INNER);
    transpose_pad<<<dim3(128 / 32,  2048 / 32), tb>>>(W_x,   wtx,   D_INNER, XDBL_W, 128);
    transpose_pad<<<dim3(2048 / 32, 64 / 32),   tb>>>(W_dt,  wtdt,  DT_RANK, D_INNER, D_INNER);
    transpose_pad<<<dim3(1024 / 32, 2048 / 32), tb>>>(W_out, wtout, D_INNER, D_MODEL, D_MODEL);

    // 1) xz = x @ W_in   (M=4096, N=4096, K=1024) — 256x128 tiles
    mma_gemm<256, 256, 0><<<dim3(4096 / 128, BL / 256), 256, SMEM_256>>>(
        xr, D_MODEL, wtin, D_MODEL, xz, nullptr, nullptr, 2 * D_INNER, 2 * D_INNER, D_MODEL, 0);

    // 2) depthwise causal conv + silu
    {
        int total = BATCH * SEQLEN * D_INNER;
        conv_silu_kernel<<<(total + 255) / 256, 256>>>(conv_w, conv_b);
    }

    // 3) x_dbl = xc @ W_x  — split-K=4 (4 x K=512), partials then rounded reduce
    mma_gemm<128, 128, 0><<<dim3(1, BL / 128, 4), 128, SMEM_128>>>(
        xc, D_INNER, wtx, D_INNER, x3p, nullptr, nullptr, XDBL_W, XDBL_W, 512, (size_t)X3N);
    reduce_x3_kernel<<<(X3N / 4 + 255) / 256, 256>>>();

    // 4) dt = softplus(x_dbl[:, :64] @ W_dt + b_dt); edt = exp(-dt)
    mma_gemm<128, 128, 1><<<dim3(2048 / 128, BL / 128), 128, SMEM_128>>>(
        xdbl, XDBL_W, wtdt, DT_RANK, dtp, edtp, b_dt, D_INNER, D_INNER, DT_RANK, 0);

    // 5) selective scan (double-buffered staging)
    scan_kernel<<<BATCH * (D_INNER / 32), 64, SCAN_SMEM>>>(A_log, Dp);

    // 6) out = y @ W_out   (M=4096, N=1024, K=2048) — 256x128 tiles
    mma_gemm<256, 256, 0><<<dim3(1024 / 128, BL / 256), 256, SMEM_256>>>(
        yp, D_INNER, wtout, D_INNER, out, nullptr, nullptr, D_MODEL, D_MODEL, D_INNER, 0);
}

// round 6
// speedup vs baseline: 2.5886x; 1.1806x over previous
#include <cuda_runtime.h>
#include <cuda_fp16.h>
#include <math.h>
#include <stdint.h>

#define BATCH 2
#define SEQLEN 2048
#define D_MODEL 1024
#define D_STATE 16
#define D_CONV 4
#define D_INNER 2048
#define DT_RANK 64

#define BL (BATCH * SEQLEN)               // 4096 rows
#define XDBL_W (DT_RANK + 2 * D_STATE)    // 96
#define X3N (BL * XDBL_W)                 // 393216

// ---------------- scratch ----------------
__device__ __half g_xr[(size_t)BL * D_MODEL];
__device__ __half g_xz[(size_t)BL * 2 * D_INNER];
__device__ __half g_xc[(size_t)BL * D_INNER];
__device__ __half g_xdbl[(size_t)BL * XDBL_W];
__device__ float  g_x3part[(size_t)4 * X3N];
__device__ float  g_dt[(size_t)BL * D_INNER];
__device__ float  g_edt[(size_t)BL * D_INNER];
__device__ __half g_y[(size_t)BL * D_INNER];
__device__ __half g_wtin[(size_t)(2 * D_INNER) * D_MODEL];
__device__ __half g_wtx[(size_t)128 * D_INNER];
__device__ __half g_wtdt[(size_t)D_INNER * DT_RANK];
__device__ __half g_wtout[(size_t)D_MODEL * D_INNER];

// ================= helpers =================
__device__ __forceinline__ uint32_t smem_u32(const void* p) {
    uint32_t a;
    asm("{ .reg .u64 t; cvta.to.shared.u64 t, %1; cvt.u32.u64 %0, t; }" : "=r"(a) : "l"(p));
    return a;
}
#define CP_ASYNC16(dst, src) \
    asm volatile("cp.async.cg.shared.global [%0], [%1], 16;" :: "r"(dst), "l"(src) : "memory")
#define CP_COMMIT() asm volatile("cp.async.commit_group;" ::: "memory")
#define CP_WAIT0()  asm volatile("cp.async.wait_group 0;" ::: "memory")
#define CP_WAIT1()  asm volatile("cp.async.wait_group 1;" ::: "memory")

__device__ __forceinline__ void mma_f16(float* c, const uint32_t* a, uint32_t b0, uint32_t b1) {
    asm volatile(
        "mma.sync.aligned.m16n8k16.row.col.f32.f16.f16.f32 "
        "{%0,%1,%2,%3}, {%4,%5,%6,%7}, {%8,%9}, {%0,%1,%2,%3};"
        : "+f"(c[0]), "+f"(c[1]), "+f"(c[2]), "+f"(c[3])
        : "r"(a[0]), "r"(a[1]), "r"(a[2]), "r"(a[3]), "r"(b0), "r"(b1));
}
__device__ __forceinline__ uint32_t lds32(uint32_t addr) {
    uint32_t v;
    asm volatile("ld.shared.b32 %0, [%1];" : "=r"(v) : "r"(addr));
    return v;
}
__device__ __forceinline__ uint32_t pack_h2(float a, float b) {
    __half2 h = __floats2half2_rn(a, b);
    return *(uint32_t*)&h;
}

// async tile load: ROWS x 64 halves (128B/row), SW128 swizzle on 16B units
template<int ROWS, int THREADS>
__device__ __forceinline__ void load_tile(const __half* __restrict__ G, int ldg,
                                          uint32_t sbase, int k0, int tid) {
#pragma unroll
    for (int u = 0; u < ROWS * 8 / THREADS; u++) {
        int i = tid + u * THREADS;
        int row = i >> 3, cu = i & 7;
        const __half* src = G + (size_t)row * ldg + k0 + cu * 8;
        uint32_t off = (uint32_t)(row * 128 + ((cu ^ (row & 7)) << 4));
        CP_ASYNC16(sbase + off, src);
    }
}

// ---------------- fp16 mma.sync GEMM: C[M,N] = A[M,K] @ Bt[N,K]^T ----------------
// BM x 128 x 64 CTA tile, warps of 64x64 (m16n8k16). Split-K via blockIdx.z.
// EPI: 0 = fp32 store, 1 = softplus/exp(-) dual fp32 (dt), 2 = fp16 store
template<int BM, int THREADS, int EPI>
__global__ __launch_bounds__(THREADS, (THREADS == 128) ? 2 : 1)
void mma_gemm(const __half* __restrict__ A, int lda,
              const __half* __restrict__ Bt, int ldb,
              float* __restrict__ C, float* __restrict__ C2,
              const float* __restrict__ bias,
              int ldc, int nvalid, int K, size_t csplit)
{
    extern __shared__ float sm[];
    const uint32_t sb = smem_u32(sm);
    constexpr uint32_t SS = (uint32_t)(BM + 128) * 128;  // bytes per stage
    constexpr int MW = BM / 64;

    const int tid = threadIdx.x;
    const int wid = tid >> 5, lane = tid & 31;
    const int wm = (wid % MW) * 64, wn = (wid / MW) * 64;
    const int q = lane >> 2, t4 = lane & 3;

    const int kbase = blockIdx.z * K;
    const __half* Ab = A  + (size_t)blockIdx.y * BM * lda + kbase;
    const __half* Bb = Bt + (size_t)blockIdx.x * 128 * ldb + kbase;
    C += csplit * blockIdx.z;

    float acc[4][8][4];
#pragma unroll
    for (int a = 0; a < 4; a++)
#pragma unroll
        for (int b = 0; b < 8; b++)
#pragma unroll
            for (int e = 0; e < 4; e++) acc[a][b][e] = 0.f;

    load_tile<BM, THREADS>(Ab, lda, sb, 0, tid);
    load_tile<128, THREADS>(Bb, ldb, sb + (uint32_t)BM * 128, 0, tid);
    CP_COMMIT();

    const int niter = K >> 6;                 // BK = 64 halves
    for (int it = 0; it < niter; it++) {
        CP_WAIT0();
        __syncthreads();
        if (it + 1 < niter) {
            uint32_t s2 = ((it + 1) & 1) ? SS : 0u;
            load_tile<BM, THREADS>(Ab, lda, sb + s2, (it + 1) << 6, tid);
            load_tile<128, THREADS>(Bb, ldb, sb + s2 + (uint32_t)BM * 128, (it + 1) << 6, tid);
            CP_COMMIT();
        }
        const uint32_t abase = sb + ((it & 1) ? SS : 0u);
        const uint32_t bbase = abase + (uint32_t)BM * 128;
#pragma unroll
        for (int kk = 0; kk < 4; kk++) {      // 4 x k16
            const uint32_t x0 = (uint32_t)(((kk * 2) ^ q) << 4);
            const uint32_t x1 = (uint32_t)(((kk * 2 + 1) ^ q) << 4);
            uint32_t ar[4][4];
#pragma unroll
            for (int mf = 0; mf < 4; mf++) {
                uint32_t base = abase + (uint32_t)((wm + mf * 16 + q) * 128 + t4 * 4);
                ar[mf][0] = lds32(base + x0);
                ar[mf][1] = lds32(base + 1024u + x0);
                ar[mf][2] = lds32(base + x1);
                ar[mf][3] = lds32(base + 1024u + x1);
            }
#pragma unroll
            for (int nf = 0; nf < 8; nf++) {
                uint32_t bbb = bbase + (uint32_t)((wn + nf * 8 + q) * 128 + t4 * 4);
                uint32_t b0 = lds32(bbb + x0);
                uint32_t b1 = lds32(bbb + x1);
#pragma unroll
                for (int mf = 0; mf < 4; mf++)
                    mma_f16(acc[mf][nf], ar[mf], b0, b1);
            }
        }
        __syncthreads();
    }

    // epilogue
#pragma unroll
    for (int mf = 0; mf < 4; mf++) {
        const int row = blockIdx.y * BM + wm + mf * 16 + q;
#pragma unroll
        for (int nf = 0; nf < 8; nf++) {
            const int col = blockIdx.x * 128 + wn + nf * 8 + t4 * 2;
            float c0 = acc[mf][nf][0], c1 = acc[mf][nf][1];
            float c2 = acc[mf][nf][2], c3 = acc[mf][nf][3];
            if (EPI == 1) {
                const float bv0 = bias[col], bv1 = bias[col + 1];
                float v0 = c0 + bv0, v1 = c1 + bv1, v2 = c2 + bv0, v3 = c3 + bv1;
                float s0 = (v0 > 20.f) ? v0 : log1pf(expf(v0));
                float s1 = (v1 > 20.f) ? v1 : log1pf(expf(v1));
                float s2 = (v2 > 20.f) ? v2 : log1pf(expf(v2));
                float s3 = (v3 > 20.f) ? v3 : log1pf(expf(v3));
                *(float2*)(C  + (size_t)row * ldc + col)       = make_float2(s0, s1);
                *(float2*)(C  + (size_t)(row + 8) * ldc + col) = make_float2(s2, s3);
                *(float2*)(C2 + (size_t)row * ldc + col)       = make_float2(expf(-s0), expf(-s1));
                *(float2*)(C2 + (size_t)(row + 8) * ldc + col) = make_float2(expf(-s2), expf(-s3));
            } else if (EPI == 2) {
                __half* Ch = (__half*)C;
                *(uint32_t*)(Ch + (size_t)row * ldc + col)       = pack_h2(c0, c1);
                *(uint32_t*)(Ch + (size_t)(row + 8) * ldc + col) = pack_h2(c2, c3);
            } else {
                if (col + 1 < nvalid) {
                    *(float2*)(C + (size_t)row * ldc + col)       = make_float2(c0, c1);
                    *(float2*)(C + (size_t)(row + 8) * ldc + col) = make_float2(c2, c3);
                }
            }
        }
    }
}

// ---------------- split-K reduce for GEMM3 (fp32 partials -> half xdbl) ----------------
__global__ void reduce_x3_kernel()
{
    int i = blockIdx.x * blockDim.x + threadIdx.x;
    const int n4 = X3N / 4;
    if (i >= n4) return;
    const float4* p = (const float4*)g_x3part;
    float4 a = p[i], b = p[i + n4], c = p[i + 2 * n4], d = p[i + 3 * n4];
    uint2 r;
    r.x = pack_h2(a.x + b.x + c.x + d.x, a.y + b.y + c.y + d.y);
    r.y = pack_h2(a.z + b.z + c.z + d.z, a.w + b.w + c.w + d.w);
    ((uint2*)g_xdbl)[i] = r;
}

// ---------------- fp32 -> fp16 convert pre-pass ----------------
__global__ void cvt_half_kernel(const float* __restrict__ src, __half* __restrict__ dst, int n4)
{
    int i = blockIdx.x * blockDim.x + threadIdx.x;
    if (i < n4) {
        float4 v = ((const float4*)src)[i];
        uint2 r;
        r.x = pack_h2(v.x, v.y);
        r.y = pack_h2(v.z, v.w);
        ((uint2*)dst)[i] = r;
    }
}

// ---------------- transpose (+ zero pad rows, fp16 out) ----------------
__global__ void transpose_pad(const float* __restrict__ src, __half* __restrict__ dst,
                              int R, int C, int Cpad)
{
    __shared__ float t[32][33];
    const int bx = blockIdx.x * 32;
    const int by = blockIdx.y * 32;
    const int tx = threadIdx.x, ty = threadIdx.y;
#pragma unroll
    for (int j = 0; j < 32; j += 8) {
        int rr = by + ty + j, cc = bx + tx;
        t[ty + j][tx] = (cc < C && rr < R) ? src[(size_t)rr * C + cc] : 0.f;
    }
    __syncthreads();
#pragma unroll
    for (int j = 0; j < 32; j += 8) {
        int dr = bx + ty + j, dc = by + tx;
        if (dr < Cpad && dc < R)
            dst[(size_t)dr * R + dc] = __float2half_rn(t[tx][ty + j]);
    }
}

// ---------------- depthwise causal conv1d + silu (half in/out) ----------------
__global__ void conv_silu_kernel(const float* __restrict__ conv_w,
                                 const float* __restrict__ conv_b)
{
    int idx = blockIdx.x * blockDim.x + threadIdx.x;
    if (idx >= BATCH * SEQLEN * D_INNER) return;
    int d = idx % D_INNER;
    int l = (idx / D_INNER) % SEQLEN;
    int b = idx / (D_INNER * SEQLEN);

    const __half* xcol = g_xz + (size_t)b * SEQLEN * (2 * D_INNER) + d;
    float acc = conv_b[d];
#pragma unroll
    for (int k = 0; k < D_CONV; k++) {
        int ll = l - (D_CONV - 1) + k;
        if (ll >= 0) acc += conv_w[d * D_CONV + k] * __half2float(xcol[(size_t)ll * (2 * D_INNER)]);
    }
    float s = 1.f / (1.f + __expf(-acc));
    g_xc[idx] = __float2half_rn(acc * s);
}

// ---------------- fused selective scan (double-buffered staging) ----------------
#define T_CHUNK 64
#define NCHUNK (SEQLEN / T_CHUNK)
// byte offsets in dynamic smem
#define SC_DT  0u          // 2 x 8192 (fp32)
#define SC_EDT 16384u      // 2 x 8192 (fp32)
#define SC_X   32768u      // 2 x 4096 (fp16)
#define SC_Z   40960u      // 2 x 4096 (fp16)
#define SC_BC  49152u      // 2 x 4096 (fp16)
#define SC_Y   57344u      // 8192 (fp32)
#define SCAN_SMEM 65536

__global__ __launch_bounds__(64)
void scan_kernel(const float* __restrict__ A_log, const float* __restrict__ Dp)
{
    extern __shared__ char scs[];
    const uint32_t sb = smem_u32(scs);

    const int tid  = threadIdx.x;
    const int b    = blockIdx.x >> 6;
    const int d0   = (blockIdx.x & 63) * 32;
    const int dl   = tid >> 1;
    const int half = tid & 1;
    const int d    = d0 + dl;

    float Avals[8];
    bool structured = true;
#pragma unroll
    for (int j = 0; j < 8; j++) {
        int n = half * 8 + j;
        float a = -expf(A_log[d * D_STATE + n]);
        Avals[j] = a;
        structured = structured && (fabsf(a + (float)(n + 1)) < 1e-3f * (float)(n + 1));
    }
    const float Dv = Dp[d];

    float h[8];
#pragma unroll
    for (int j = 0; j < 8; j++) h[j] = 0.f;

    const size_t base_row = (size_t)b * SEQLEN;

    auto stage = [&](int l0, int s) {
        const size_t row = base_row + l0 + tid;
        const float*  pdt  = g_dt   + row * D_INNER + d0;
        const float*  pedt = g_edt  + row * D_INNER + d0;
        const __half* px   = g_xc   + row * D_INNER + d0;
        const __half* pz   = g_xz   + row * (2 * D_INNER) + D_INNER + d0;
        const __half* pbc  = g_xdbl + row * XDBL_W + DT_RANK;
        const uint32_t so32 = (uint32_t)(s * 8192) + (uint32_t)tid * 128;
        const uint32_t so16 = (uint32_t)(s * 4096) + (uint32_t)tid * 64;
#pragma unroll
        for (int qq = 0; qq < 8; qq++) {
            CP_ASYNC16(sb + SC_DT  + so32 + qq * 16, pdt  + qq * 4);
            CP_ASYNC16(sb + SC_EDT + so32 + qq * 16, pedt + qq * 4);
        }
#pragma unroll
        for (int qq = 0; qq < 4; qq++) {
            CP_ASYNC16(sb + SC_X  + so16 + qq * 16, px  + qq * 8);
            CP_ASYNC16(sb + SC_Z  + so16 + qq * 16, pz  + qq * 8);
            CP_ASYNC16(sb + SC_BC + so16 + qq * 16, pbc + qq * 8);
        }
        CP_COMMIT();
    };

    stage(0, 0);

    for (int c = 0; c < NCHUNK; c++) {
        const int s = c & 1;
        if (c + 1 < NCHUNK) {
            stage((c + 1) * T_CHUNK, s ^ 1);
            CP_WAIT1();
        } else {
            CP_WAIT0();
        }
        __syncthreads();

        const float*  fdt  = (const float*) (scs + SC_DT  + s * 8192);
        const float*  fedt = (const float*) (scs + SC_EDT + s * 8192);
        const __half* fx   = (const __half*)(scs + SC_X   + s * 4096);
        const __half* fz   = (const __half*)(scs + SC_Z   + s * 4096);
        const __half* fbc  = (const __half*)(scs + SC_BC  + s * 4096);
        float* fy = (float*)(scs + SC_Y);

        for (int t = 0; t < T_CHUNK; t++) {
            float dt = fdt[t * 32 + dl];
            float x  = __half2float(fx[t * 32 + dl]);
            float dA[8];
            if (structured) {
                float e1 = fedt[t * 32 + dl];
                float e2 = e1 * e1;
                float e4 = e2 * e2;
                float p  = half ? (e4 * e4) : 1.0f;
#pragma unroll
                for (int j = 0; j < 8; j++) { p *= e1; dA[j] = p; }
            } else {
#pragma unroll
                for (int j = 0; j < 8; j++) dA[j] = __expf(dt * Avals[j]);
            }
            float dtx = dt * x;
            float y0 = 0.f, y1 = 0.f;
#pragma unroll
            for (int j = 0; j < 8; j++) {
                float Bn = __half2float(fbc[t * 32 + half * 8 + j]);
                float Cn = __half2float(fbc[t * 32 + 16 + half * 8 + j]);
                h[j] = dA[j] * h[j] + dtx * Bn;
                if (j & 1) y1 += h[j] * Cn; else y0 += h[j] * Cn;
            }
            float y = y0 + y1;
            y += __shfl_xor_sync(0xffffffffu, y, 1);
            if (half == 0) {
                float zv  = __half2float(fz[t * 32 + dl]);
                float sig = 1.f / (1.f + __expf(-zv));
                fy[t * 32 + dl] = (y + Dv * x) * (zv * sig);
            }
        }
        __syncthreads();

        {
            const size_t row = base_row + c * T_CHUNK + tid;
            uint2* py = (uint2*)(g_y + row * D_INNER + d0);
            const float* fy = (const float*)(scs + SC_Y);
#pragma unroll
            for (int qq = 0; qq < 8; qq++) {
                uint2 r;
                r.x = pack_h2(fy[tid * 32 + qq * 4 + 0], fy[tid * 32 + qq * 4 + 1]);
                r.y = pack_h2(fy[tid * 32 + qq * 4 + 2], fy[tid * 32 + qq * 4 + 3]);
                py[qq] = r;
            }
        }
        __syncthreads();
    }
}

// ---------------- launch ----------------
#define SMEM_128 65536
#define SMEM_256 98304

extern "C" void kernel_launch(void* const* d_in, const int* in_sizes, int n_in,
                              void* d_out, int out_size)
{
    const float* x      = (const float*)d_in[0];
    const float* W_in   = (const float*)d_in[1];
    const float* conv_w = (const float*)d_in[2];
    const float* conv_b = (const float*)d_in[3];
    const float* W_x    = (const float*)d_in[4];
    const float* W_dt   = (const float*)d_in[5];
    const float* b_dt   = (const float*)d_in[6];
    const float* A_log  = (const float*)d_in[7];
    const float* Dp     = (const float*)d_in[8];
    const float* W_out  = (const float*)d_in[9];
    float* out = (float*)d_out;

    __half* xr    = nullptr; cudaGetSymbolAddress((void**)&xr,    g_xr);
    __half* xz    = nullptr; cudaGetSymbolAddress((void**)&xz,    g_xz);
    __half* xc    = nullptr; cudaGetSymbolAddress((void**)&xc,    g_xc);
    __half* xdbl  = nullptr; cudaGetSymbolAddress((void**)&xdbl,  g_xdbl);
    float*  x3p   = nullptr; cudaGetSymbolAddress((void**)&x3p,   g_x3part);
    float*  dtp   = nullptr; cudaGetSymbolAddress((void**)&dtp,   g_dt);
    float*  edtp  = nullptr; cudaGetSymbolAddress((void**)&edtp,  g_edt);
    __half* yp    = nullptr; cudaGetSymbolAddress((void**)&yp,    g_y);
    __half* wtin  = nullptr; cudaGetSymbolAddress((void**)&wtin,  g_wtin);
    __half* wtx   = nullptr; cudaGetSymbolAddress((void**)&wtx,   g_wtx);
    __half* wtdt  = nullptr; cudaGetSymbolAddress((void**)&wtdt,  g_wtdt);
    __half* wtout = nullptr; cudaGetSymbolAddress((void**)&wtout, g_wtout);

    cudaFuncSetAttribute((const void*)mma_gemm<128, 128, 0>, cudaFuncAttributeMaxDynamicSharedMemorySize, SMEM_128);
    cudaFuncSetAttribute((const void*)mma_gemm<128, 128, 1>, cudaFuncAttributeMaxDynamicSharedMemorySize, SMEM_128);
    cudaFuncSetAttribute((const void*)mma_gemm<256, 256, 0>, cudaFuncAttributeMaxDynamicSharedMemorySize, SMEM_256);
    cudaFuncSetAttribute((const void*)mma_gemm<256, 256, 2>, cudaFuncAttributeMaxDynamicSharedMemorySize, SMEM_256);
    cudaFuncSetAttribute((const void*)scan_kernel, cudaFuncAttributeMaxDynamicSharedMemorySize, SCAN_SMEM);

    // x -> fp16
    cvt_half_kernel<<<(BL * D_MODEL / 4 + 255) / 256, 256>>>(x, xr, BL * D_MODEL / 4);

    // weight transposes (K-major, fp16)
    dim3 tb(32, 8);
    transpose_pad<<<dim3(4096 / 32, 1024 / 32), tb>>>(W_in,  wtin,  D_MODEL, 2 * D_INNER, 2 * D_INNER);
    transpose_pad<<<dim3(128 / 32,  2048 / 32), tb>>>(W_x,   wtx,   D_INNER, XDBL_W, 128);
    transpose_pad<<<dim3(2048 / 32, 64 / 32),   tb>>>(W_dt,  wtdt,  DT_RANK, D_INNER, D_INNER);
    transpose_pad<<<dim3(1024 / 32, 2048 / 32), tb>>>(W_out, wtout, D_INNER, D_MODEL, D_MODEL);

    // 1) xz = x @ W_in  (M=4096, N=4096, K=1024) — fp16 out
    mma_gemm<256, 256, 2><<<dim3(4096 / 128, BL / 256), 256, SMEM_256>>>(
        xr, D_MODEL, wtin, D_MODEL, (float*)xz, nullptr, nullptr, 2 * D_INNER, 2 * D_INNER, D_MODEL, 0);

    // 2) depthwise causal conv + silu
    {
        int total = BATCH * SEQLEN * D_INNER;
        conv_silu_kernel<<<(total + 255) / 256, 256>>>(conv_w, conv_b);
    }

    // 3) x_dbl = xc @ W_x — split-K=4 (4 x K=512), fp32 partials, reduce -> half
    mma_gemm<128, 128, 0><<<dim3(1, BL / 128, 4), 128, SMEM_128>>>(
        xc, D_INNER, wtx, D_INNER, x3p, nullptr, nullptr, XDBL_W, XDBL_W, 512, (size_t)X3N);
    reduce_x3_kernel<<<(X3N / 4 + 255) / 256, 256>>>();

    // 4) dt = softplus(x_dbl[:, :64] @ W_dt + b_dt); edt = exp(-dt)  (fp32 outs)
    mma_gemm<128, 128, 1><<<dim3(2048 / 128, BL / 128), 128, SMEM_128>>>(
        xdbl, XDBL_W, wtdt, DT_RANK, dtp, edtp, b_dt, D_INNER, D_INNER, DT_RANK, 0);

    // 5) selective scan -> y (fp16)
    scan_kernel<<<BATCH * (D_INNER / 32), 64, SCAN_SMEM>>>(A_log, Dp);

    // 6) out = y @ W_out  (M=4096, N=1024, K=2048) — fp32 out
    mma_gemm<256, 256, 0><<<dim3(1024 / 128, BL / 256), 256, SMEM_256>>>(
        yp, D_INNER, wtout, D_INNER, out, nullptr, nullptr, D_MODEL, D_MODEL, D_INNER, 0);
}